// round 9
// baseline (speedup 1.0000x reference)
#include <cuda_runtime.h>
#include <cuda_bf16.h>
#include <cstdint>

#define NB      32
#define NRINGS  10
#define NANG    36
#define NPTS    (NRINGS * NANG)     // 360
#define NTGT    16384
#define NCHUNK  32
#define TC      (NTGT / NCHUNK)     // 512 targets per chunk (compile-time)
#define TPB     (NRINGS * 32)       // 320 threads: warp = ring
#define NBLK    (NCHUNK * NB)       // 1024 blocks -> ~7 tiles/SM, ~1.4% imbalance

// Monotone-encoded running max of -d2 per (batch,point). Zero = -inf sentinel;
// the last block resets everything after the reduce so graph replays are clean.
__device__ unsigned int g_keys[NB * NPTS];
__device__ unsigned int g_count;

__device__ __forceinline__ unsigned int enc_f32(float f) {
    unsigned int u = __float_as_uint(f);
    return ((int)u < 0) ? ~u : (u | 0x80000000u);
}
__device__ __forceinline__ float dec_f32(unsigned int k) {
    unsigned int u = ((int)k < 0) ? (k & 0x7FFFFFFFu) : ~k;
    return __uint_as_float(u);
}

// Paired angles (a, 36-a): shared-cos FFMA, then +/-S*V. Constants = FFMA imms.
#define PAIR2(IA, IB, CV, SV)                        \
    { float P = fmaf(CV, U, Acc);                    \
      m[IA] = fminf(m[IA], fmaf( SV, V, P));         \
      m[IB] = fminf(m[IB], fmaf(-SV, V, P)); }

// Full 36-angle evaluation: 4 axis angles + 16 mirror pairs. 88 instr/target.
__device__ __forceinline__ void eval36(float m[NANG], float U, float V, float Acc) {
    m[ 0] = fminf(m[ 0], Acc + U);
    m[18] = fminf(m[18], Acc - U);
    m[ 9] = fminf(m[ 9], Acc + V);
    m[27] = fminf(m[27], Acc - V);
    PAIR2( 1, 35,  0.9848077530f, 0.1736481777f)
    PAIR2( 2, 34,  0.9396926208f, 0.3420201433f)
    PAIR2( 3, 33,  0.8660254038f, 0.5f)
    PAIR2( 4, 32,  0.7660444431f, 0.6427876097f)
    PAIR2( 5, 31,  0.6427876097f, 0.7660444431f)
    PAIR2( 6, 30,  0.5f,          0.8660254038f)
    PAIR2( 7, 29,  0.3420201433f, 0.9396926208f)
    PAIR2( 8, 28,  0.1736481777f, 0.9848077530f)
    PAIR2(10, 26, -0.1736481777f, 0.9848077530f)
    PAIR2(11, 25, -0.3420201433f, 0.9396926208f)
    PAIR2(12, 24, -0.5f,          0.8660254038f)
    PAIR2(13, 23, -0.6427876097f, 0.7660444431f)
    PAIR2(14, 22, -0.7660444431f, 0.6427876097f)
    PAIR2(15, 21, -0.8660254038f, 0.5f)
    PAIR2(16, 20, -0.9396926208f, 0.3420201433f)
    PAIR2(17, 19, -0.9848077530f, 0.1736481777f)
}

__global__ void __launch_bounds__(TPB)
chamfer_fused_kernel(const float* __restrict__ pred,
                     const float* __restrict__ target,
                     float* __restrict__ out)
{
    __shared__ float4 sm[TC];
    __shared__ float  wsum[NRINGS];
    __shared__ unsigned int is_last;

    const int chunk = blockIdx.x;
    const int b     = blockIdx.y;
    const int tid   = threadIdx.x;

    // Stage + preprocess: (2tx-0.08, -2ty, -2tz, t2-0.08tx)
    const float* tg = target + ((size_t)b * NTGT + (size_t)chunk * TC) * 3;
    for (int i = tid; i < TC; i += TPB) {
        float tx = tg[i * 3 + 0];
        float ty = tg[i * 3 + 1];
        float tz = tg[i * 3 + 2];
        float t2 = tx * tx + ty * ty + tz * tz;
        sm[i] = make_float4(2.0f * tx - 0.08f, -2.0f * ty, -2.0f * tz,
                            fmaf(-0.08f, tx, t2));
    }
    __syncthreads();

    const int ring = tid >> 5;
    const int lane = tid & 31;

    const float r  = pred[b * NRINGS + ring];
    const float py = 0.15f * (float)ring - 0.7f;
    const float Kr = fmaf(r, r, fmaf(py, py, 0.0016f));
    const unsigned int pbase = (unsigned)(b * NPTS + ring * NANG);
    const float INF = __int_as_float(0x7f800000);

    float m[NANG];
    #pragma unroll
    for (int a = 0; a < NANG; a++) m[a] = INF;

    #pragma unroll 2
    for (int t = lane; t < TC; t += 32) {
        float4 v  = sm[t];
        float Acc = fmaf(py, v.y, v.w) + Kr;
        float U   = r * v.x;
        float V   = r * v.z;
        eval36(m, U, V, Acc);
    }

    // Butterfly min across lanes per angle, fold into g_keys via REDG.MAX.
    #pragma unroll
    for (int a = 0; a < NANG; a++) {
        float x = m[a];
        #pragma unroll
        for (int o = 16; o > 0; o >>= 1)
            x = fminf(x, __shfl_xor_sync(0xffffffffu, x, o));
        if (lane == (a & 31))
            atomicMax(&g_keys[pbase + a], enc_f32(-x));
    }

    // ---- last-block finalize (fused; no second kernel) ----
    __threadfence();
    if (tid == 0)
        is_last = (atomicAdd(&g_count, 1u) == (unsigned)(NBLK - 1));
    __syncthreads();
    if (!is_last) return;
    __threadfence();

    uint4* keys4 = (uint4*)g_keys;
    const int n4 = (NB * NPTS) / 4;     // 2880
    float s = 0.0f;
    for (int i = tid; i < n4; i += TPB) {
        uint4 k = keys4[i];
        s += fmaxf(-dec_f32(k.x), 0.0f);
        s += fmaxf(-dec_f32(k.y), 0.0f);
        s += fmaxf(-dec_f32(k.z), 0.0f);
        s += fmaxf(-dec_f32(k.w), 0.0f);
    }
    #pragma unroll
    for (int o = 16; o > 0; o >>= 1) s += __shfl_down_sync(0xffffffffu, s, o);
    if (lane == 0) wsum[ring] = s;
    __syncthreads();
    if (tid == 0) {
        float tot = 0.0f;
        #pragma unroll
        for (int w = 0; w < NRINGS; w++) tot += wsum[w];
        out[0] = tot / (float)(NB * NPTS);
    }
    __syncthreads();   // all g_keys reads complete before reset

    const uint4 z4 = make_uint4(0u, 0u, 0u, 0u);
    for (int i = tid; i < n4; i += TPB) keys4[i] = z4;
    if (tid == 0) g_count = 0u;
}

extern "C" void kernel_launch(void* const* d_in, const int* in_sizes, int n_in,
                              void* d_out, int out_size) {
    const float* pred   = (const float*)d_in[0];   // (32, 10)
    const float* target = (const float*)d_in[1];   // (32, 16384, 3)
    float* out = (float*)d_out;

    dim3 grid(NCHUNK, NB);
    chamfer_fused_kernel<<<grid, TPB>>>(pred, target, out);
}

// round 10
// speedup vs baseline: 1.2673x; 1.2673x over previous
#include <cuda_runtime.h>
#include <cuda_bf16.h>
#include <cstdint>

#define NB      32
#define NRINGS  10
#define NANG    36
#define NPTS    (NRINGS * NANG)     // 360
#define NTGT    16384
#define TPB     (NRINGS * 32)       // 320 threads: warp = ring
#define NBLK    444                 // = 148 SMs x 3 resident -> exactly one wave
#define NBIG    392                 // batches 0..27: 14 blocks x 37 groups
#define NG_BIG  37                  // 14*37*32 = 16576 >= 16384 (dup-clamped tail)
#define NG_SML  40                  // 13*40*32 = 16640 >= 16384
#define MAXT    (NG_SML * 32)       // 1280 staged targets (20 KB smem)

// Monotone-encoded running max of -d2 per (batch,point). Zero = -inf sentinel;
// the last block resets everything after the reduce so graph replays are clean.
__device__ unsigned int g_keys[NB * NPTS];
__device__ unsigned int g_count;

__device__ __forceinline__ unsigned int enc_f32(float f) {
    unsigned int u = __float_as_uint(f);
    return ((int)u < 0) ? ~u : (u | 0x80000000u);
}
__device__ __forceinline__ float dec_f32(unsigned int k) {
    unsigned int u = ((int)k < 0) ? (k & 0x7FFFFFFFu) : ~k;
    return __uint_as_float(u);
}

// Paired angles (a, 36-a): shared-cos FFMA, then +/-S*V. Constants = FFMA imms.
#define PAIR2(IA, IB, CV, SV)                        \
    { float P = fmaf(CV, U, Acc);                    \
      m[IA] = fminf(m[IA], fmaf( SV, V, P));         \
      m[IB] = fminf(m[IB], fmaf(-SV, V, P)); }

__device__ __forceinline__ void eval36(float m[NANG], float U, float V, float Acc) {
    m[ 0] = fminf(m[ 0], Acc + U);
    m[18] = fminf(m[18], Acc - U);
    m[ 9] = fminf(m[ 9], Acc + V);
    m[27] = fminf(m[27], Acc - V);
    PAIR2( 1, 35,  0.9848077530f, 0.1736481777f)
    PAIR2( 2, 34,  0.9396926208f, 0.3420201433f)
    PAIR2( 3, 33,  0.8660254038f, 0.5f)
    PAIR2( 4, 32,  0.7660444431f, 0.6427876097f)
    PAIR2( 5, 31,  0.6427876097f, 0.7660444431f)
    PAIR2( 6, 30,  0.5f,          0.8660254038f)
    PAIR2( 7, 29,  0.3420201433f, 0.9396926208f)
    PAIR2( 8, 28,  0.1736481777f, 0.9848077530f)
    PAIR2(10, 26, -0.1736481777f, 0.9848077530f)
    PAIR2(11, 25, -0.3420201433f, 0.9396926208f)
    PAIR2(12, 24, -0.5f,          0.8660254038f)
    PAIR2(13, 23, -0.6427876097f, 0.7660444431f)
    PAIR2(14, 22, -0.7660444431f, 0.6427876097f)
    PAIR2(15, 21, -0.8660254038f, 0.5f)
    PAIR2(16, 20, -0.9396926208f, 0.3420201433f)
    PAIR2(17, 19, -0.9848077530f, 0.1736481777f)
}

// Mainloop with compile-time trip count. All lanes read valid staged data
// (duplicates from index clamping are harmless for min).
template<int NG>
__device__ __forceinline__ void run_tile(float m[NANG], const float4* __restrict__ sm,
                                         int lane, float r, float py, float Kr)
{
    #pragma unroll 2
    for (int it = 0; it < NG; it++) {
        float4 v  = sm[it * 32 + lane];
        float Acc = fmaf(py, v.y, v.w) + Kr;
        float U   = r * v.x;
        float V   = r * v.z;
        eval36(m, U, V, Acc);
    }
}

__global__ void __launch_bounds__(TPB)
chamfer_fused_kernel(const float* __restrict__ pred,
                     const float* __restrict__ target,
                     float* __restrict__ out)
{
    __shared__ float4 sm[MAXT];
    __shared__ float  wsum[NRINGS];
    __shared__ unsigned int is_last;

    const int bid = blockIdx.x;
    const int tid = threadIdx.x;

    // Block -> (batch, within-batch tile). Batches 0..27: 14 tiles of 37 groups;
    // batches 28..31: 13 tiles of 40 groups. Every block is single-batch.
    int batch, wb, ng;
    if (bid < NBIG) { batch = bid / 14;            wb = bid - batch * 14;        ng = NG_BIG; }
    else            { int e = bid - NBIG; int q = e / 13;
                      batch = 28 + q;              wb = e - q * 13;              ng = NG_SML; }

    const int start = wb * ng * 32;                 // within-batch target start
    const int n     = ng * 32;

    // Stage + preprocess with clamped (duplicated) tail:
    // (2tx-0.08, -2ty, -2tz, t2-0.08tx)
    const float* tg = target + (size_t)batch * NTGT * 3;
    for (int i = tid; i < n; i += TPB) {
        int gi = min(start + i, NTGT - 1);
        float tx = tg[gi * 3 + 0];
        float ty = tg[gi * 3 + 1];
        float tz = tg[gi * 3 + 2];
        float t2 = tx * tx + ty * ty + tz * tz;
        sm[i] = make_float4(2.0f * tx - 0.08f, -2.0f * ty, -2.0f * tz,
                            fmaf(-0.08f, tx, t2));
    }
    __syncthreads();

    const int ring = tid >> 5;
    const int lane = tid & 31;

    const float r  = pred[batch * NRINGS + ring];
    const float py = 0.15f * (float)ring - 0.7f;
    const float Kr = fmaf(r, r, fmaf(py, py, 0.0016f));
    const unsigned int pbase = (unsigned)(batch * NPTS + ring * NANG);
    const float INF = __int_as_float(0x7f800000);

    float m[NANG];
    #pragma unroll
    for (int a = 0; a < NANG; a++) m[a] = INF;

    if (ng == NG_BIG) run_tile<NG_BIG>(m, sm, lane, r, py, Kr);
    else              run_tile<NG_SML>(m, sm, lane, r, py, Kr);

    // One fold per block: butterfly min per angle, REDG.MAX into g_keys.
    #pragma unroll
    for (int a = 0; a < NANG; a++) {
        float x = m[a];
        #pragma unroll
        for (int o = 16; o > 0; o >>= 1)
            x = fminf(x, __shfl_xor_sync(0xffffffffu, x, o));
        if (lane == (a & 31))
            atomicMax(&g_keys[pbase + a], enc_f32(-x));
    }

    // ---- last-block finalize (fused; no second kernel) ----
    __threadfence();
    if (tid == 0)
        is_last = (atomicAdd(&g_count, 1u) == (unsigned)(NBLK - 1));
    __syncthreads();
    if (!is_last) return;
    __threadfence();

    uint4* keys4 = (uint4*)g_keys;
    const int n4 = (NB * NPTS) / 4;     // 2880
    float s = 0.0f;
    for (int i = tid; i < n4; i += TPB) {
        uint4 k = keys4[i];
        s += fmaxf(-dec_f32(k.x), 0.0f);
        s += fmaxf(-dec_f32(k.y), 0.0f);
        s += fmaxf(-dec_f32(k.z), 0.0f);
        s += fmaxf(-dec_f32(k.w), 0.0f);
    }
    #pragma unroll
    for (int o = 16; o > 0; o >>= 1) s += __shfl_down_sync(0xffffffffu, s, o);
    if (lane == 0) wsum[ring] = s;
    __syncthreads();
    if (tid == 0) {
        float tot = 0.0f;
        #pragma unroll
        for (int w = 0; w < NRINGS; w++) tot += wsum[w];
        out[0] = tot / (float)(NB * NPTS);
    }
    __syncthreads();   // all g_keys reads complete before reset

    const uint4 z4 = make_uint4(0u, 0u, 0u, 0u);
    for (int i = tid; i < n4; i += TPB) keys4[i] = z4;
    if (tid == 0) g_count = 0u;
}

extern "C" void kernel_launch(void* const* d_in, const int* in_sizes, int n_in,
                              void* d_out, int out_size) {
    const float* pred   = (const float*)d_in[0];   // (32, 10)
    const float* target = (const float*)d_in[1];   // (32, 16384, 3)
    float* out = (float*)d_out;

    chamfer_fused_kernel<<<NBLK, TPB>>>(pred, target, out);
}